// round 15
// baseline (speedup 1.0000x reference)
#include <cuda_runtime.h>
#include <cuda_fp16.h>
#include <math.h>
#include <stdint.h>

#define BATCH   8192
#define DIM     256
#define NTOT    5376      // 256 + 1024 + 4096
#define BM      128
#define BN      128
#define NT      42        // n-tiles: 2 (L1) + 8 (L2) + 32 (L3)
#define ASTR    272       // smem row stride in BYTES (256 data + 16 pad)

// dynamic smem layout (bytes)
#define OFF_XSQ  0          // 128 floats
#define OFF_SX   512        // 128 floats (2*sx per row)
#define OFF_WSQ  1024       // 128 floats
#define OFF_SW   1536       // 128 floats (sw per col)
#define OFF_RED  2048       // 128 rows x 2 warp_n x 4 ull = 8192
#define OFF_A    10240      // 128 * 272 = 34816
#define OFF_B    45056      // 128 * 272 = 34816
#define SMEM_TOTAL 79872    // -> 2 CTAs/SM

__device__ __align__(16) uint8_t g_Xq[BATCH * DIM];   // e4m3, 2.0 MB
__device__ __align__(16) uint8_t g_Wq[NTOT * DIM];    // e4m3, 1.3 MB
__device__ float g_xsq[BATCH];
__device__ float g_wsq[NTOT];
__device__ float g_sx[BATCH];    // per-row dequant scale (max/448)
__device__ float g_sw[NTOT];
__device__ unsigned long long g_cand[(size_t)BATCH * NT * 4];

// ---------------------------------------------------------------------------
__device__ __forceinline__ uint32_t smem_u32(const void* p) {
    uint32_t a;
    asm("{ .reg .u64 t; cvta.to.shared.u64 t, %1; cvt.u32.u64 %0, t; }"
        : "=r"(a) : "l"(p));
    return a;
}
__device__ __forceinline__ unsigned fkey(float f) {
    unsigned u = __float_as_uint(f);
    return (u & 0x80000000u) ? ~u : (u | 0x80000000u);
}
__device__ __forceinline__ float finv(unsigned m) {
    unsigned u = (m & 0x80000000u) ? (m & 0x7fffffffu) : ~m;
    return __uint_as_float(u);
}
__device__ __forceinline__ void ins4(unsigned long long k, unsigned long long t[4]) {
    if (k < t[3]) {
        t[3] = k;
        if (t[3] < t[2]) { unsigned long long z = t[2]; t[2] = t[3]; t[3] = z; }
        if (t[2] < t[1]) { unsigned long long z = t[1]; t[1] = t[2]; t[2] = z; }
        if (t[1] < t[0]) { unsigned long long z = t[0]; t[0] = t[1]; t[1] = z; }
    }
}

#define CP16(d, s) \
    asm volatile("cp.async.cg.shared.global [%0], [%1], 16;" :: "r"(d), "l"(s))

#define LDSM_X4(r0, r1, r2, r3, a) \
    asm volatile("ldmatrix.sync.aligned.m8n8.x4.shared.b16 {%0,%1,%2,%3}, [%4];" \
        : "=r"(r0), "=r"(r1), "=r"(r2), "=r"(r3) : "r"(a))

// fp8 e4m3 MMA, fp32 accumulate (sm_89+ standard PTX)
#define FMMA16832(d, a, b0, b1) \
    asm volatile("mma.sync.aligned.m16n8k32.row.col.f32.e4m3.e4m3.f32 " \
        "{%0,%1,%2,%3}, {%4,%5,%6,%7}, {%8,%9}, {%0,%1,%2,%3};" \
        : "+f"((d)[0]), "+f"((d)[1]), "+f"((d)[2]), "+f"((d)[3]) \
        : "r"((a)[0]), "r"((a)[1]), "r"((a)[2]), "r"((a)[3]), \
          "r"(b0), "r"(b1))

// ---------------------------------------------------------------------------
// conv: warp per row. Per-row max-abs scaling to e4m3, exact fp32 norm.
// ---------------------------------------------------------------------------
__global__ void som_conv(const float* __restrict__ x,
                         const float* __restrict__ w1,
                         const float* __restrict__ w2,
                         const float* __restrict__ w3) {
    int gw = (blockIdx.x * blockDim.x + threadIdx.x) >> 5;
    int lane = threadIdx.x & 31;
    if (gw >= BATCH + NTOT) return;
    const float* src;
    uint8_t* dst;
    float *nrm, *scl;
    if (gw < BATCH) {
        src = x + (size_t)gw * DIM;
        dst = g_Xq + (size_t)gw * DIM;
        nrm = g_xsq + gw; scl = g_sx + gw;
    } else {
        int n = gw - BATCH;
        if (n < 256)       src = w1 + (size_t)n * DIM;
        else if (n < 1280) src = w2 + (size_t)(n - 256) * DIM;
        else               src = w3 + (size_t)(n - 1280) * DIM;
        dst = g_Wq + (size_t)n * DIM;
        nrm = g_wsq + n; scl = g_sw + n;
    }
    float4 a = ((const float4*)src)[lane * 2];
    float4 b = ((const float4*)src)[lane * 2 + 1];
    float v[8] = { a.x, a.y, a.z, a.w, b.x, b.y, b.z, b.w };
    float s = 0.f, mx = 0.f;
    #pragma unroll
    for (int i = 0; i < 8; i++) { s += v[i] * v[i]; mx = fmaxf(mx, fabsf(v[i])); }
    #pragma unroll
    for (int o = 16; o; o >>= 1) {
        s  += __shfl_xor_sync(0xffffffffu, s, o);
        mx  = fmaxf(mx, __shfl_xor_sync(0xffffffffu, mx, o));
    }
    mx = fmaxf(mx, 1e-30f);
    float qs = 448.0f / mx;
    float q[8];
    #pragma unroll
    for (int i = 0; i < 8; i++) q[i] = v[i] * qs;
    // pack 8 e4m3: byte i = element i (little-endian)
    unsigned short p01, p23, p45, p67;
    asm("cvt.rn.satfinite.e4m3x2.f32 %0, %1, %2;" : "=h"(p01) : "f"(q[1]), "f"(q[0]));
    asm("cvt.rn.satfinite.e4m3x2.f32 %0, %1, %2;" : "=h"(p23) : "f"(q[3]), "f"(q[2]));
    asm("cvt.rn.satfinite.e4m3x2.f32 %0, %1, %2;" : "=h"(p45) : "f"(q[5]), "f"(q[4]));
    asm("cvt.rn.satfinite.e4m3x2.f32 %0, %1, %2;" : "=h"(p67) : "f"(q[7]), "f"(q[6]));
    uint2 pk;
    pk.x = (unsigned)p01 | ((unsigned)p23 << 16);
    pk.y = (unsigned)p45 | ((unsigned)p67 << 16);
    ((uint2*)dst)[lane] = pk;
    if (lane == 0) { *nrm = s; *scl = mx / 448.0f; }
}

// ---------------------------------------------------------------------------
// main: fp8 e4m3 MMA GEMM 128x128 tile, K=256 fully smem-resident (2 halves,
// half-1 load overlaps half-0 compute). 256 threads (8 warps), warp grid
// 4(m) x 2(n), warp tile 32x64 = 2(m16) x 8(n8) MMAs per k32 step.
// grid = (64, 42), 2 CTAs/SM. Fused top-4 argmin per (row, tile).
// ---------------------------------------------------------------------------
__device__ __forceinline__ void prefetch_half(uint32_t bA, uint32_t bB,
                                              const uint8_t* gA,
                                              const uint8_t* gB,
                                              int half, int tid) {
    #pragma unroll
    for (int it = 0; it < 4; it++) {
        int idx = tid + it * 256;          // 0..1023
        int r = idx >> 3;                  // 0..127
        int g = idx & 7;                   // 16B group within 128B half
        uint32_t off = (uint32_t)(r * ASTR + half * 128 + g * 16);
        CP16(bA + off, gA + (size_t)r * DIM + half * 128 + g * 16);
        CP16(bB + off, gB + (size_t)r * DIM + half * 128 + g * 16);
    }
    asm volatile("cp.async.commit_group;" ::: "memory");
}

__global__ __launch_bounds__(256, 2)
void som_mma() {
    extern __shared__ char smem[];
    float* s_xsq = (float*)(smem + OFF_XSQ);
    float* s_sx  = (float*)(smem + OFF_SX);
    float* s_wsq = (float*)(smem + OFF_WSQ);
    float* s_sw  = (float*)(smem + OFF_SW);
    unsigned long long* s_red = (unsigned long long*)(smem + OFF_RED);
    uint32_t sb = smem_u32(smem);

    int tid = threadIdx.x, L = tid & 31, wid = tid >> 5;
    int warp_m = wid & 3, warp_n = wid >> 2;
    int yt = blockIdx.y;

    int n0, wsqOff;
    if (yt < 2)       { n0 = yt * BN;        wsqOff = 0;    }
    else if (yt < 10) { n0 = (yt - 2) * BN;  wsqOff = 256;  }
    else              { n0 = (yt - 10) * BN; wsqOff = 1280; }

    int row0 = blockIdx.x * BM;
    const uint8_t* gA = g_Xq + (size_t)row0 * DIM;
    const uint8_t* gB = g_Wq + (size_t)(wsqOff + n0) * DIM;

    prefetch_half(sb + OFF_A, sb + OFF_B, gA, gB, 0, tid);
    prefetch_half(sb + OFF_A, sb + OFF_B, gA, gB, 1, tid);

    if (tid < 128) {
        s_xsq[tid] = g_xsq[row0 + tid];
        s_sx[tid]  = 2.0f * g_sx[row0 + tid];
        s_wsq[tid] = g_wsq[wsqOff + n0 + tid];
        s_sw[tid]  = g_sw[wsqOff + n0 + tid];
    }

    float acc[2][8][4];
    #pragma unroll
    for (int i = 0; i < 2; i++)
        #pragma unroll
        for (int j = 0; j < 8; j++)
            #pragma unroll
            for (int q = 0; q < 4; q++) acc[i][j][q] = 0.f;

    #pragma unroll
    for (int half = 0; half < 2; half++) {
        if (half == 0)
            asm volatile("cp.async.wait_group 1;" ::: "memory");
        else
            asm volatile("cp.async.wait_group 0;" ::: "memory");
        __syncthreads();

        #pragma unroll
        for (int kk = 0; kk < 4; kk++) {            // k32 steps within half
            uint32_t kbyte = (uint32_t)(half * 128 + kk * 32);
            uint32_t a[2][4];
            #pragma unroll
            for (int i = 0; i < 2; i++) {
                int row = warp_m * 32 + i * 16 + (L & 15);
                uint32_t addr = sb + OFF_A + (uint32_t)row * ASTR + kbyte
                              + (uint32_t)(L >> 4) * 16;
                LDSM_X4(a[i][0], a[i][1], a[i][2], a[i][3], addr);
            }
            uint32_t b[8][2];
            #pragma unroll
            for (int jp = 0; jp < 4; jp++) {
                int n = warp_n * 64 + jp * 16 + ((L >> 4) & 1) * 8 + (L & 7);
                uint32_t koff = ((L >> 3) & 1) * 16;
                uint32_t addr = sb + OFF_B + (uint32_t)n * ASTR + kbyte + koff;
                uint32_t r0, r1, r2, r3;
                LDSM_X4(r0, r1, r2, r3, addr);
                b[2 * jp][0] = r0;     b[2 * jp][1] = r1;
                b[2 * jp + 1][0] = r2; b[2 * jp + 1][1] = r3;
            }
            #pragma unroll
            for (int i = 0; i < 2; i++)
                #pragma unroll
                for (int j = 0; j < 8; j++)
                    FMMA16832(acc[i][j], a[i], b[j][0], b[j][1]);
        }
    }

    // ------------- epilogue: scores + per-row top-4 over this tile ----------
    unsigned long long t4[4][4];
    #pragma unroll
    for (int r = 0; r < 4; r++)
        #pragma unroll
        for (int s = 0; s < 4; s++) t4[r][s] = ~0ull;

    #pragma unroll
    for (int i = 0; i < 2; i++) {
        #pragma unroll
        for (int half = 0; half < 2; half++) {
            int ridx = i * 2 + half;
            int row = warp_m * 32 + i * 16 + (L >> 2) + half * 8;
            float xq = s_xsq[row];
            float tsx = s_sx[row];           // 2*sx
            #pragma unroll
            for (int j = 0; j < 8; j++) {
                int nb = warp_n * 64 + j * 8 + 2 * (L & 3);
                float d0 = acc[i][j][half * 2 + 0];
                float d1 = acc[i][j][half * 2 + 1];
                float s0 = xq + s_wsq[nb]     - tsx * s_sw[nb]     * d0;
                float s1 = xq + s_wsq[nb + 1] - tsx * s_sw[nb + 1] * d1;
                unsigned long long k0 =
                    (((unsigned long long)fkey(s0)) << 32) | (unsigned)(n0 + nb);
                unsigned long long k1 =
                    (((unsigned long long)fkey(s1)) << 32) | (unsigned)(n0 + nb + 1);
                ins4(k0, t4[ridx]);
                ins4(k1, t4[ridx]);
            }
        }
    }

    // quad reduction (lanes L^1, L^2 share the same rows)
    #pragma unroll
    for (int off = 1; off < 4; off <<= 1) {
        #pragma unroll
        for (int r = 0; r < 4; r++) {
            unsigned long long o0 = __shfl_xor_sync(0xffffffffu, t4[r][0], off);
            unsigned long long o1 = __shfl_xor_sync(0xffffffffu, t4[r][1], off);
            unsigned long long o2 = __shfl_xor_sync(0xffffffffu, t4[r][2], off);
            unsigned long long o3 = __shfl_xor_sync(0xffffffffu, t4[r][3], off);
            ins4(o0, t4[r]); ins4(o1, t4[r]); ins4(o2, t4[r]); ins4(o3, t4[r]);
        }
    }
    if ((L & 3) == 0) {
        #pragma unroll
        for (int i = 0; i < 2; i++)
            #pragma unroll
            for (int half = 0; half < 2; half++) {
                int ridx = i * 2 + half;
                int row = warp_m * 32 + i * 16 + (L >> 2) + half * 8;
                #pragma unroll
                for (int s = 0; s < 4; s++)
                    s_red[row * 8 + warp_n * 4 + s] = t4[ridx][s];
            }
    }
    __syncthreads();

    if (tid < 128) {
        unsigned long long m[4];
        #pragma unroll
        for (int s = 0; s < 4; s++) m[s] = s_red[tid * 8 + s];
        #pragma unroll
        for (int s = 0; s < 4; s++) ins4(s_red[tid * 8 + 4 + s], m);
        size_t gi = ((size_t)(row0 + tid) * NT + yt) * 4;
        #pragma unroll
        for (int s = 0; s < 4; s++) g_cand[gi + s] = m[s];
    }
}

// ---------------------------------------------------------------------------
// stage2: one warp per (level,row). Warp-parallel exact fp32 rescore of all
// candidates within thr of approx min; exact argmin + exact q_err; outputs.
// ---------------------------------------------------------------------------
__global__ void som_stage2(const float* __restrict__ x,
                           const float* __restrict__ w1,
                           const float* __restrict__ w2,
                           const float* __restrict__ w3,
                           float* __restrict__ out) {
    int gw = (blockIdx.x * blockDim.x + threadIdx.x) >> 5;
    int lane = threadIdx.x & 31;
    if (gw >= 3 * BATCH) return;
    int level = gw / BATCH;
    int row = gw - level * BATCH;

    const int t0s[3]  = { 0, 2, 10 };
    const int nts[3]  = { 2, 8, 32 };
    const int offs[3] = { 0, 256, 1280 };
    int t0 = t0s[level], ncand = nts[level] * 4;
    const float* w = (level == 0) ? w1 : ((level == 1) ? w2 : w3);
    int side = 16 << level;

    size_t cbase = ((size_t)row * NT + t0) * 4;
    unsigned long long cand[4] = { ~0ull, ~0ull, ~0ull, ~0ull };
    #pragma unroll
    for (int ci = 0; ci < 4; ci++) {
        int idx = lane * 4 + ci;
        if (idx < ncand) cand[ci] = g_cand[cbase + idx];
    }

    const float INF = __int_as_float(0x7f800000);
    float m = INF;
    #pragma unroll
    for (int ci = 0; ci < 4; ci++)
        if (cand[ci] != ~0ull) m = fminf(m, finv((unsigned)(cand[ci] >> 32)));
    #pragma unroll
    for (int o = 16; o; o >>= 1) m = fminf(m, __shfl_xor_sync(0xffffffffu, m, o));
    float thr = m + 12.0f;    // widened for fp8 score noise (std ~1.6)

    float xsq = g_xsq[row];
    const float4* xr = (const float4*)(x + (size_t)row * DIM);
    float4 xa = xr[lane], xb = xr[lane + 32];

    unsigned long long ebest = ~0ull;
    float ed2 = 0.f;
    #pragma unroll
    for (int ci = 0; ci < 4; ci++) {
        bool pass = (cand[ci] != ~0ull) &&
                    (finv((unsigned)(cand[ci] >> 32)) <= thr);
        unsigned mask = __ballot_sync(0xffffffffu, pass);
        while (mask) {
            int src = __ffs(mask) - 1;
            mask &= mask - 1;
            unsigned long long k = __shfl_sync(0xffffffffu, cand[ci], src);
            int n = (int)(k & 0xffffffffu);
            const float4* wr = (const float4*)(w + (size_t)n * DIM);
            float4 wa = wr[lane], wb = wr[lane + 32];
            float dot = xa.x * wa.x + xa.y * wa.y + xa.z * wa.z + xa.w * wa.w
                      + xb.x * wb.x + xb.y * wb.y + xb.z * wb.z + xb.w * wb.w;
            float dx0 = xa.x - wa.x, dx1 = xa.y - wa.y,
                  dx2 = xa.z - wa.z, dx3 = xa.w - wa.w;
            float dy0 = xb.x - wb.x, dy1 = xb.y - wb.y,
                  dy2 = xb.z - wb.z, dy3 = xb.w - wb.w;
            float df = dx0 * dx0 + dx1 * dx1 + dx2 * dx2 + dx3 * dx3
                     + dy0 * dy0 + dy1 * dy1 + dy2 * dy2 + dy3 * dy3;
            #pragma unroll
            for (int o = 16; o; o >>= 1) {
                dot += __shfl_xor_sync(0xffffffffu, dot, o);
                df  += __shfl_xor_sync(0xffffffffu, df, o);
            }
            float sc = xsq + g_wsq[offs[level] + n] - 2.0f * dot;
            unsigned long long ek =
                (((unsigned long long)fkey(sc)) << 32) | (unsigned)n;
            if (ek < ebest) { ebest = ek; ed2 = df; }
        }
    }

    if (lane == 0) {
        int n = (int)(ebest & 0xffffffffu);
        out[level * (2 * BATCH) + 2 * row + 0] = (float)(n / side);
        out[level * (2 * BATCH) + 2 * row + 1] = (float)(n % side);
        out[3 * (2 * BATCH) + level * BATCH + row] = sqrtf(ed2 < 0.f ? 0.f : ed2);
    }
}

// ---------------------------------------------------------------------------
extern "C" void kernel_launch(void* const* d_in, const int* in_sizes, int n_in,
                              void* d_out, int out_size) {
    const float *x = nullptr, *w1 = nullptr, *w2 = nullptr, *w3 = nullptr;
    for (int i = 0; i < n_in; i++) {
        switch (in_sizes[i]) {
            case 8192 * 256: x  = (const float*)d_in[i]; break;
            case 256 * 256:  w1 = (const float*)d_in[i]; break;
            case 1024 * 256: w2 = (const float*)d_in[i]; break;
            case 4096 * 256: w3 = (const float*)d_in[i]; break;
            default: break;
        }
    }
    float* out = (float*)d_out;

    cudaFuncSetAttribute(som_mma, cudaFuncAttributeMaxDynamicSharedMemorySize,
                         SMEM_TOTAL);

    som_conv<<<(BATCH + NTOT + 7) / 8, 256>>>(x, w1, w2, w3);

    dim3 grid(BATCH / BM, NT);
    som_mma<<<grid, 256, SMEM_TOTAL>>>();

    som_stage2<<<3 * BATCH / 8, 256>>>(x, w1, w2, w3, out);
}

// round 17
// speedup vs baseline: 1.6198x; 1.6198x over previous
#include <cuda_runtime.h>
#include <cuda_fp16.h>
#include <math.h>
#include <stdint.h>

#define BATCH   8192
#define DIM     256
#define NTOT    5376      // 256 + 1024 + 4096
#define BM      128
#define BN      128
#define NT      42        // n-tiles: 2 (L1) + 8 (L2) + 32 (L3)
#define BK      64
#define NCHUNK  4         // 256 / 64
#define ASTR    72        // padded smem row stride in fp16 (144B)

// dynamic smem layout (bytes)
#define OFF_XSQ  0          // 128 floats
#define OFF_WSQ  512        // 128 floats
#define OFF_TILE 1024       // 6 buffers: A0 A1 A2 B0 B1 B2
#define TILE_BYTES 18432
#define SMEM_TOTAL (OFF_TILE + 6 * TILE_BYTES)   // 111616 -> 2 CTAs/SM

__device__ __align__(16) __half g_Xe[BATCH * DIM];   // 4.2 MB
__device__ __align__(16) __half g_We[NTOT * DIM];    // 2.75 MB
__device__ float g_xsq[BATCH];
__device__ float g_wsq[NTOT];
__device__ unsigned long long g_cand[(size_t)BATCH * NT * 4];

// ---------------------------------------------------------------------------
__device__ __forceinline__ uint32_t smem_u32(const void* p) {
    uint32_t a;
    asm("{ .reg .u64 t; cvta.to.shared.u64 t, %1; cvt.u32.u64 %0, t; }"
        : "=r"(a) : "l"(p));
    return a;
}
__device__ __forceinline__ unsigned fkey(float f) {
    unsigned u = __float_as_uint(f);
    return (u & 0x80000000u) ? ~u : (u | 0x80000000u);
}
__device__ __forceinline__ float finv(unsigned m) {
    unsigned u = (m & 0x80000000u) ? (m & 0x7fffffffu) : ~m;
    return __uint_as_float(u);
}
__device__ __forceinline__ unsigned long long umin64(unsigned long long a,
                                                     unsigned long long b) {
    return a < b ? a : b;
}
__device__ __forceinline__ unsigned long long umax64(unsigned long long a,
                                                     unsigned long long b) {
    return a > b ? a : b;
}
// branchless top-2 insert
__device__ __forceinline__ void ins2(unsigned long long k,
                                     unsigned long long& t1,
                                     unsigned long long& t2) {
    unsigned long long lo = umin64(k, t1);
    t2 = umin64(t2, umax64(k, t1));
    t1 = lo;
}

#define CP16(d, s) \
    asm volatile("cp.async.cg.shared.global [%0], [%1], 16;" :: "r"(d), "l"(s))

#define LDSM_X4(r0, r1, r2, r3, a) \
    asm volatile("ldmatrix.sync.aligned.m8n8.x4.shared.b16 {%0,%1,%2,%3}, [%4];" \
        : "=r"(r0), "=r"(r1), "=r"(r2), "=r"(r3) : "r"(a))

// fp16-accumulate HMMA: C/D fragment = 2 regs (4 halves)
#define MMA16816H(d, a, b0, b1) \
    asm volatile("mma.sync.aligned.m16n8k16.row.col.f16.f16.f16.f16 " \
        "{%0,%1}, {%2,%3,%4,%5}, {%6,%7}, {%0,%1};" \
        : "+r"((d)[0]), "+r"((d)[1]) \
        : "r"((a)[0]), "r"((a)[1]), "r"((a)[2]), "r"((a)[3]), \
          "r"(b0), "r"(b1))

// ---------------------------------------------------------------------------
// conv: warp per row. 2x float4 loads, packed fp16x2 stores, shfl reduction.
// ---------------------------------------------------------------------------
__global__ void som_conv(const float* __restrict__ x,
                         const float* __restrict__ w1,
                         const float* __restrict__ w2,
                         const float* __restrict__ w3) {
    int gw = (blockIdx.x * blockDim.x + threadIdx.x) >> 5;
    int lane = threadIdx.x & 31;
    if (gw >= BATCH + NTOT) return;
    const float* src;
    __half* dst;
    float* nrm;
    if (gw < BATCH) {
        src = x + (size_t)gw * DIM;
        dst = g_Xe + (size_t)gw * DIM;
        nrm = g_xsq + gw;
    } else {
        int n = gw - BATCH;
        if (n < 256)       src = w1 + (size_t)n * DIM;
        else if (n < 1280) src = w2 + (size_t)(n - 256) * DIM;
        else               src = w3 + (size_t)(n - 1280) * DIM;
        dst = g_We + (size_t)n * DIM;
        nrm = g_wsq + n;
    }
    float4 a = ((const float4*)src)[lane * 2];
    float4 b = ((const float4*)src)[lane * 2 + 1];
    __half2 h0 = __floats2half2_rn(a.x, a.y);
    __half2 h1 = __floats2half2_rn(a.z, a.w);
    __half2 h2 = __floats2half2_rn(b.x, b.y);
    __half2 h3 = __floats2half2_rn(b.z, b.w);
    uint4 pk;
    pk.x = *(unsigned*)&h0; pk.y = *(unsigned*)&h1;
    pk.z = *(unsigned*)&h2; pk.w = *(unsigned*)&h3;
    ((uint4*)dst)[lane] = pk;
    float s = a.x * a.x + a.y * a.y + a.z * a.z + a.w * a.w
            + b.x * b.x + b.y * b.y + b.z * b.z + b.w * b.w;
    #pragma unroll
    for (int o = 16; o; o >>= 1) s += __shfl_xor_sync(0xffffffffu, s, o);
    if (lane == 0) *nrm = s;
}

// ---------------------------------------------------------------------------
// main: fp16-acc mma.sync GEMM 128x128 tile, K=256 in 4 BK=64 chunks,
// 3-stage cp.async pipeline, one barrier per chunk, 2 CTAs/SM.
// grid = (64, 42), 256 threads (8 warps), warp grid 4(m) x 2(n).
// Lean epilogue: branchless per-warp_n top-2, direct global writes.
// ---------------------------------------------------------------------------
__device__ __forceinline__ void prefetch_chunk(uint32_t bA, uint32_t bB,
                                               const __half* gA,
                                               const __half* gB,
                                               int k0, int tid) {
    #pragma unroll
    for (int it = 0; it < 4; it++) {
        int idx = tid + it * 256;          // 0..1023
        int r = idx >> 3;                  // 0..127
        int g = idx & 7;                   // 16B group within 64 fp16
        uint32_t off = (uint32_t)(r * ASTR + g * 8) * 2;
        CP16(bA + off, gA + (size_t)r * DIM + k0 + g * 8);
        CP16(bB + off, gB + (size_t)r * DIM + k0 + g * 8);
    }
    asm volatile("cp.async.commit_group;" ::: "memory");
}

__global__ __launch_bounds__(256, 2)
void som_mma() {
    extern __shared__ char smem[];
    float* s_xsq = (float*)(smem + OFF_XSQ);
    float* s_wsq = (float*)(smem + OFF_WSQ);
    uint32_t sb = smem_u32(smem);

    int tid = threadIdx.x, L = tid & 31, wid = tid >> 5;
    int warp_m = wid & 3, warp_n = wid >> 2;
    int yt = blockIdx.y;

    int n0, wsqOff;
    if (yt < 2)       { n0 = yt * BN;        wsqOff = 0;    }
    else if (yt < 10) { n0 = (yt - 2) * BN;  wsqOff = 256;  }
    else              { n0 = (yt - 10) * BN; wsqOff = 1280; }

    int row0 = blockIdx.x * BM;
    const __half* gA = g_Xe + (size_t)row0 * DIM;
    const __half* gB = g_We + (size_t)(wsqOff + n0) * DIM;

    // stage s: A at OFF_TILE + s*TILE, B at OFF_TILE + (3+s)*TILE
    prefetch_chunk(sb + OFF_TILE + 0 * TILE_BYTES,
                   sb + OFF_TILE + 3 * TILE_BYTES, gA, gB, 0 * BK, tid);
    prefetch_chunk(sb + OFF_TILE + 1 * TILE_BYTES,
                   sb + OFF_TILE + 4 * TILE_BYTES, gA, gB, 1 * BK, tid);
    prefetch_chunk(sb + OFF_TILE + 2 * TILE_BYTES,
                   sb + OFF_TILE + 5 * TILE_BYTES, gA, gB, 2 * BK, tid);

    if (tid < 128) {
        s_xsq[tid] = g_xsq[row0 + tid];
        s_wsq[tid] = g_wsq[wsqOff + n0 + tid];
    }

    uint32_t acc[2][8][2];            // fp16x2 accumulators
    #pragma unroll
    for (int i = 0; i < 2; i++)
        #pragma unroll
        for (int j = 0; j < 8; j++) { acc[i][j][0] = 0u; acc[i][j][1] = 0u; }

    #pragma unroll
    for (int c = 0; c < NCHUNK; c++) {
        if (c == 0)      asm volatile("cp.async.wait_group 2;" ::: "memory");
        else if (c == 3) asm volatile("cp.async.wait_group 0;" ::: "memory");
        else             asm volatile("cp.async.wait_group 1;" ::: "memory");
        __syncthreads();

        if (c == 1)
            prefetch_chunk(sb + OFF_TILE + 0 * TILE_BYTES,
                           sb + OFF_TILE + 3 * TILE_BYTES, gA, gB, 3 * BK, tid);

        int st = c % 3;
        uint32_t bA = sb + OFF_TILE + (uint32_t)st * TILE_BYTES;
        uint32_t bB = sb + OFF_TILE + (uint32_t)(3 + st) * TILE_BYTES;
        #pragma unroll
        for (int kk = 0; kk < 4; kk++) {
            uint32_t a[2][4];
            #pragma unroll
            for (int i = 0; i < 2; i++) {
                int row = warp_m * 32 + i * 16 + (L & 15);
                uint32_t addr = bA + (uint32_t)(row * ASTR + kk * 16 + (L >> 4) * 8) * 2;
                LDSM_X4(a[i][0], a[i][1], a[i][2], a[i][3], addr);
            }
            uint32_t b[8][2];
            #pragma unroll
            for (int jp = 0; jp < 4; jp++) {
                int n = warp_n * 64 + jp * 16 + ((L >> 4) & 1) * 8 + (L & 7);
                uint32_t koff = ((L >> 3) & 1) * 8;
                uint32_t addr = bB + (uint32_t)(n * ASTR + kk * 16 + koff) * 2;
                uint32_t r0, r1, r2, r3;
                LDSM_X4(r0, r1, r2, r3, addr);
                b[2 * jp][0] = r0;     b[2 * jp][1] = r1;
                b[2 * jp + 1][0] = r2; b[2 * jp + 1][1] = r3;
            }
            #pragma unroll
            for (int i = 0; i < 2; i++)
                #pragma unroll
                for (int j = 0; j < 8; j++)
                    MMA16816H(acc[i][j], a[i], b[j][0], b[j][1]);
        }
    }

    // ------- lean epilogue: per-warp_n branchless top-2, direct global ------
    unsigned long long t1[4], t2[4];
    #pragma unroll
    for (int r = 0; r < 4; r++) { t1[r] = ~0ull; t2[r] = ~0ull; }

    #pragma unroll
    for (int i = 0; i < 2; i++) {
        #pragma unroll
        for (int half = 0; half < 2; half++) {     // half = C-fragment reg
            int ridx = i * 2 + half;
            int row = warp_m * 32 + i * 16 + (L >> 2) + half * 8;
            float xq = s_xsq[row];
            #pragma unroll
            for (int j = 0; j < 8; j++) {
                int nb = warp_n * 64 + j * 8 + 2 * (L & 3);
                __half2 h = *(__half2*)&acc[i][j][half];
                float d0 = __low2float(h);
                float d1 = __high2float(h);
                float s0 = xq + s_wsq[nb]     - 2.0f * d0;
                float s1 = xq + s_wsq[nb + 1] - 2.0f * d1;
                unsigned long long k0 =
                    (((unsigned long long)fkey(s0)) << 32) | (unsigned)(n0 + nb);
                unsigned long long k1 =
                    (((unsigned long long)fkey(s1)) << 32) | (unsigned)(n0 + nb + 1);
                ins2(k0, t1[ridx], t2[ridx]);
                ins2(k1, t1[ridx], t2[ridx]);
            }
        }
    }

    // quad reduction (lanes L^1, L^2 share the same rows): merge sorted pairs
    #pragma unroll
    for (int off = 1; off < 4; off <<= 1) {
        #pragma unroll
        for (int r = 0; r < 4; r++) {
            unsigned long long o1 = __shfl_xor_sync(0xffffffffu, t1[r], off);
            unsigned long long o2 = __shfl_xor_sync(0xffffffffu, t2[r], off);
            unsigned long long lo = umin64(t1[r], o1);
            t2[r] = umin64(umin64(t2[r], o2), umax64(t1[r], o1));
            t1[r] = lo;
        }
    }
    if ((L & 3) == 0) {
        #pragma unroll
        for (int i = 0; i < 2; i++)
            #pragma unroll
            for (int half = 0; half < 2; half++) {
                int ridx = i * 2 + half;
                int row = warp_m * 32 + i * 16 + (L >> 2) + half * 8;
                size_t gi = ((size_t)(row0 + row) * NT + yt) * 4 + warp_n * 2;
                g_cand[gi]     = t1[ridx];
                g_cand[gi + 1] = t2[ridx];
            }
    }
}

// ---------------------------------------------------------------------------
// stage2: one warp per (level,row). Warp-parallel exact fp32 rescore of all
// candidates within thr of approx min; exact argmin + exact q_err; outputs.
// ---------------------------------------------------------------------------
__global__ void som_stage2(const float* __restrict__ x,
                           const float* __restrict__ w1,
                           const float* __restrict__ w2,
                           const float* __restrict__ w3,
                           float* __restrict__ out) {
    int gw = (blockIdx.x * blockDim.x + threadIdx.x) >> 5;
    int lane = threadIdx.x & 31;
    if (gw >= 3 * BATCH) return;
    int level = gw / BATCH;
    int row = gw - level * BATCH;

    const int t0s[3]  = { 0, 2, 10 };
    const int nts[3]  = { 2, 8, 32 };
    const int offs[3] = { 0, 256, 1280 };
    int t0 = t0s[level], ncand = nts[level] * 4;
    const float* w = (level == 0) ? w1 : ((level == 1) ? w2 : w3);
    int side = 16 << level;

    size_t cbase = ((size_t)row * NT + t0) * 4;
    unsigned long long cand[4] = { ~0ull, ~0ull, ~0ull, ~0ull };
    #pragma unroll
    for (int ci = 0; ci < 4; ci++) {
        int idx = lane * 4 + ci;
        if (idx < ncand) cand[ci] = g_cand[cbase + idx];
    }

    const float INF = __int_as_float(0x7f800000);
    float m = INF;
    #pragma unroll
    for (int ci = 0; ci < 4; ci++)
        if (cand[ci] != ~0ull) m = fminf(m, finv((unsigned)(cand[ci] >> 32)));
    #pragma unroll
    for (int o = 16; o; o >>= 1) m = fminf(m, __shfl_xor_sync(0xffffffffu, m, o));
    float thr = m + 1.6f;

    float xsq = g_xsq[row];
    const float4* xr = (const float4*)(x + (size_t)row * DIM);
    float4 xa = xr[lane], xb = xr[lane + 32];

    unsigned long long ebest = ~0ull;
    float ed2 = 0.f;
    #pragma unroll
    for (int ci = 0; ci < 4; ci++) {
        bool pass = (cand[ci] != ~0ull) &&
                    (finv((unsigned)(cand[ci] >> 32)) <= thr);
        unsigned mask = __ballot_sync(0xffffffffu, pass);
        while (mask) {
            int src = __ffs(mask) - 1;
            mask &= mask - 1;
            unsigned long long k = __shfl_sync(0xffffffffu, cand[ci], src);
            int n = (int)(k & 0xffffffffu);
            const float4* wr = (const float4*)(w + (size_t)n * DIM);
            float4 wa = wr[lane], wb = wr[lane + 32];
            float dot = xa.x * wa.x + xa.y * wa.y + xa.z * wa.z + xa.w * wa.w
                      + xb.x * wb.x + xb.y * wb.y + xb.z * wb.z + xb.w * wb.w;
            float dx0 = xa.x - wa.x, dx1 = xa.y - wa.y,
                  dx2 = xa.z - wa.z, dx3 = xa.w - wa.w;
            float dy0 = xb.x - wb.x, dy1 = xb.y - wb.y,
                  dy2 = xb.z - wb.z, dy3 = xb.w - wb.w;
            float df = dx0 * dx0 + dx1 * dx1 + dx2 * dx2 + dx3 * dx3
                     + dy0 * dy0 + dy1 * dy1 + dy2 * dy2 + dy3 * dy3;
            #pragma unroll
            for (int o = 16; o; o >>= 1) {
                dot += __shfl_xor_sync(0xffffffffu, dot, o);
                df  += __shfl_xor_sync(0xffffffffu, df, o);
            }
            float sc = xsq + g_wsq[offs[level] + n] - 2.0f * dot;
            unsigned long long ek =
                (((unsigned long long)fkey(sc)) << 32) | (unsigned)n;
            if (ek < ebest) { ebest = ek; ed2 = df; }
        }
    }

    if (lane == 0) {
        int n = (int)(ebest & 0xffffffffu);
        out[level * (2 * BATCH) + 2 * row + 0] = (float)(n / side);
        out[level * (2 * BATCH) + 2 * row + 1] = (float)(n % side);
        out[3 * (2 * BATCH) + level * BATCH + row] = sqrtf(ed2 < 0.f ? 0.f : ed2);
    }
}

// ---------------------------------------------------------------------------
extern "C" void kernel_launch(void* const* d_in, const int* in_sizes, int n_in,
                              void* d_out, int out_size) {
    const float *x = nullptr, *w1 = nullptr, *w2 = nullptr, *w3 = nullptr;
    for (int i = 0; i < n_in; i++) {
        switch (in_sizes[i]) {
            case 8192 * 256: x  = (const float*)d_in[i]; break;
            case 256 * 256:  w1 = (const float*)d_in[i]; break;
            case 1024 * 256: w2 = (const float*)d_in[i]; break;
            case 4096 * 256: w3 = (const float*)d_in[i]; break;
            default: break;
        }
    }
    float* out = (float*)d_out;

    cudaFuncSetAttribute(som_mma, cudaFuncAttributeMaxDynamicSharedMemorySize,
                         SMEM_TOTAL);

    som_conv<<<(BATCH + NTOT + 7) / 8, 256>>>(x, w1, w2, w3);

    dim3 grid(BATCH / BM, NT);
    som_mma<<<grid, 256, SMEM_TOTAL>>>();

    som_stage2<<<3 * BATCH / 8, 256>>>(x, w1, w2, w3, out);
}